// round 7
// baseline (speedup 1.0000x reference)
#include <cuda_runtime.h>
#include <cstdint>

#define BATCH 32
#define NSEQ 2048
#define DHEAD 128
#define TQ 128
#define TK 64
#define THREADS 256
#define KSTRIDE 136   // Q/K smem row stride (floats); 136 mod 32 = 8 -> LDS.64 row-frags conflict-free
#define VSTRIDE 132   // V smem row stride (floats); 132 mod 32 = 4 -> LDS.32 col-frags conflict-free
#define INV_SCALE 0.088388347648318447f  // 1/sqrt(128)

// smem layout (floats): Q, K[2], V[2]
#define SM_Q_OFF 0
#define SM_K_OFF (TQ * KSTRIDE)
#define SM_V_OFF (SM_K_OFF + 2 * TK * KSTRIDE)
#define SM_FLOATS (SM_V_OFF + 2 * TK * VSTRIDE)
#define SM_BYTES (SM_FLOATS * 4)

__device__ __forceinline__ float f2tf32(float x) {
    uint32_t u;
    asm("cvt.rna.tf32.f32 %0, %1;" : "=r"(u) : "f"(x));
    return __uint_as_float(u);
}

__device__ __forceinline__ void mma_tf32(float* c, const uint32_t* a, const uint32_t* b) {
    asm volatile(
        "mma.sync.aligned.m16n8k8.row.col.f32.tf32.tf32.f32 "
        "{%0,%1,%2,%3},{%4,%5,%6,%7},{%8,%9},{%0,%1,%2,%3};\n"
        : "+f"(c[0]), "+f"(c[1]), "+f"(c[2]), "+f"(c[3])
        : "r"(a[0]), "r"(a[1]), "r"(a[2]), "r"(a[3]), "r"(b[0]), "r"(b[1]));
}

__device__ __forceinline__ float4 cvt4(float4 v) {
    return make_float4(f2tf32(v.x), f2tf32(v.y), f2tf32(v.z), f2tf32(v.w));
}

// plain row-major copy (tf32-rounded): unit u -> row u>>5, float4-chunk u&31
template <int STRIDE>
__device__ __forceinline__ void sts_unit(float* dst, int u, float4 v) {
    *(float4*)(dst + (u >> 5) * STRIDE + (u & 31) * 4) = cvt4(v);
}

__global__ void __launch_bounds__(THREADS, 1)
attn_kernel(const float* __restrict__ gq, const float* __restrict__ gk,
            const float* __restrict__ gv, float* __restrict__ gattn,
            float* __restrict__ gout) {
    extern __shared__ float sm[];
    float* Qs = sm + SM_Q_OFF;

    const int qt = blockIdx.x;
    const int b = blockIdx.y;
    const int tid = threadIdx.x;
    const int wid = tid >> 5;
    const int lane = tid & 31;
    const int lq = lane >> 2;  // 0..7
    const int lr = lane & 3;   // 0..3

    const int wrow = wid * 16;                 // warp's first row within q-tile
    const int gi0 = qt * TQ + wrow + lq;       // global query row (pair: gi0, gi0+8)
    const int kt_hi = 2 * qt + 1;              // last key tile touching causal region

    // ---- prologue fills: Q (once), K0, V0 into buffer 0 ----
    {
        const float4* q4 = (const float4*)(gq + ((size_t)b * NSEQ + (size_t)qt * TQ) * DHEAD);
        for (int u = tid; u < TQ * 32; u += THREADS) sts_unit<KSTRIDE>(Qs, u, q4[u]);
        const float4* k4 = (const float4*)(gk + (size_t)b * NSEQ * DHEAD);
        for (int u = tid; u < TK * 32; u += THREADS) sts_unit<KSTRIDE>(sm + SM_K_OFF, u, k4[u]);
        const float4* v4 = (const float4*)(gv + (size_t)b * NSEQ * DHEAD);
        for (int u = tid; u < TK * 32; u += THREADS) sts_unit<VSTRIDE>(sm + SM_V_OFF, u, v4[u]);
    }

    float o[16][4];
#pragma unroll
    for (int nf = 0; nf < 16; nf++) {
        o[nf][0] = 0.f; o[nf][1] = 0.f; o[nf][2] = 0.f; o[nf][3] = 0.f;
    }
    float lsum_a = 0.f, lsum_b = 0.f;

    float* attn_row_a = gattn + ((size_t)b * NSEQ + gi0) * NSEQ;
    float* attn_row_b = attn_row_a + (size_t)8 * NSEQ;

    __syncthreads();

    for (int kt = 0; kt <= kt_hi; kt++) {
        const bool has_next = (kt < kt_hi);
        const int cur = kt & 1;
        float* Ks = sm + SM_K_OFF + cur * (TK * KSTRIDE);
        float* Vs = sm + SM_V_OFF + cur * (TK * VSTRIDE);
        float* Kn = sm + SM_K_OFF + (cur ^ 1) * (TK * KSTRIDE);
        float* Vn = sm + SM_V_OFF + (cur ^ 1) * (TK * VSTRIDE);

        // ---- register-prefetch next K tile ----
        float4 kp[8];
        if (has_next) {
            const float4* k4 = (const float4*)(gk + ((size_t)b * NSEQ + (size_t)(kt + 1) * TK) * DHEAD);
#pragma unroll
            for (int j = 0; j < 8; j++) kp[j] = k4[tid + j * THREADS];
        }

        // ---- S = Q K^T  (warp: 16 rows x 64 cols) ----
        // k-slice mapping: MMA k-slot lr -> d = 8*ks+2*lr, slot lr+4 -> d = 8*ks+2*lr+1
        float c[8][4];
#pragma unroll
        for (int nf = 0; nf < 8; nf++) {
            c[nf][0] = 0.f; c[nf][1] = 0.f; c[nf][2] = 0.f; c[nf][3] = 0.f;
        }
#pragma unroll
        for (int ks = 0; ks < 16; ks++) {
            uint32_t a[4];
            float2 a01 = *(const float2*)(Qs + (wrow + lq) * KSTRIDE + ks * 8 + 2 * lr);
            float2 a23 = *(const float2*)(Qs + (wrow + lq + 8) * KSTRIDE + ks * 8 + 2 * lr);
            a[0] = __float_as_uint(a01.x);
            a[2] = __float_as_uint(a01.y);
            a[1] = __float_as_uint(a23.x);
            a[3] = __float_as_uint(a23.y);
#pragma unroll
            for (int nf = 0; nf < 8; nf++) {
                float2 bv = *(const float2*)(Ks + (nf * 8 + lq) * KSTRIDE + ks * 8 + 2 * lr);
                uint32_t bb[2];
                bb[0] = __float_as_uint(bv.x);
                bb[1] = __float_as_uint(bv.y);
                mma_tf32(c[nf], a, bb);
            }
        }

        // ---- register-prefetch next V tile ----
        float4 vp[8];
        if (has_next) {
            const float4* v4 = (const float4*)(gv + ((size_t)b * NSEQ + (size_t)(kt + 1) * TK) * DHEAD);
#pragma unroll
            for (int j = 0; j < 8; j++) vp[j] = v4[tid + j * THREADS];
        }

        // ---- exp (unnormalized), accumulate l, write attn, tf32-round P in regs ----
#pragma unroll
        for (int nf = 0; nf < 8; nf++) {
            int j0 = kt * TK + nf * 8 + 2 * lr;
            float p00 = (j0     <= gi0)     ? __expf(c[nf][0] * INV_SCALE) : 0.f;
            float p01 = (j0 + 1 <= gi0)     ? __expf(c[nf][1] * INV_SCALE) : 0.f;
            float p10 = (j0     <= gi0 + 8) ? __expf(c[nf][2] * INV_SCALE) : 0.f;
            float p11 = (j0 + 1 <= gi0 + 8) ? __expf(c[nf][3] * INV_SCALE) : 0.f;
            lsum_a += p00 + p01;
            lsum_b += p10 + p11;
            *(float2*)(attn_row_a + j0) = make_float2(p00, p01);
            *(float2*)(attn_row_b + j0) = make_float2(p10, p11);
            c[nf][0] = f2tf32(p00);
            c[nf][1] = f2tf32(p01);
            c[nf][2] = f2tf32(p10);
            c[nf][3] = f2tf32(p11);
        }

        // ---- O += P @ V  (A = c-regs; B = V rows, 2x LDS.32 per frag) ----
#pragma unroll
        for (int ks = 0; ks < 8; ks++) {
            uint32_t a[4];
            a[0] = __float_as_uint(c[ks][0]);
            a[1] = __float_as_uint(c[ks][2]);
            a[2] = __float_as_uint(c[ks][1]);
            a[3] = __float_as_uint(c[ks][3]);
            const float* vr0 = Vs + (ks * 8 + 2 * lr) * VSTRIDE + lq;
            const float* vr1 = vr0 + VSTRIDE;
#pragma unroll
            for (int nf = 0; nf < 16; nf++) {
                uint32_t bb[2];
                bb[0] = __float_as_uint(vr0[nf * 8]);
                bb[1] = __float_as_uint(vr1[nf * 8]);
                mma_tf32(o[nf], a, bb);
            }
        }

        // ---- store prefetched K/V into the ALTERNATE buffer (no wait needed) ----
        if (has_next) {
#pragma unroll
            for (int j = 0; j < 8; j++) sts_unit<KSTRIDE>(Kn, tid + j * THREADS, kp[j]);
#pragma unroll
            for (int j = 0; j < 8; j++) sts_unit<VSTRIDE>(Vn, tid + j * THREADS, vp[j]);
        }
        __syncthreads();   // single sync: buffer flip
    }

    // ---- row sums (warp-local: full key range per warp) ----
    lsum_a += __shfl_xor_sync(0xffffffffu, lsum_a, 1);
    lsum_a += __shfl_xor_sync(0xffffffffu, lsum_a, 2);
    lsum_b += __shfl_xor_sync(0xffffffffu, lsum_b, 1);
    lsum_b += __shfl_xor_sync(0xffffffffu, lsum_b, 2);
    const float linv_a = 1.0f / lsum_a;
    const float linv_b = 1.0f / lsum_b;

    const int jz = (kt_hi + 1) * TK;   // causal extent of this q-tile

    // ---- zero-fill the strictly-masked key region (j >= jz) ----
    if (jz < NSEQ) {
        const int zc4 = (NSEQ - jz) >> 2;
        const float4 z4 = make_float4(0.f, 0.f, 0.f, 0.f);
        float* base = gattn + ((size_t)b * NSEQ + (size_t)qt * TQ) * NSEQ + jz;
        for (int i = tid; i < TQ * zc4; i += THREADS) {
            int r = i / zc4;
            int cc = i - r * zc4;
            *(float4*)(base + (size_t)r * NSEQ + cc * 4) = z4;
        }
    }

    // ---- write O (normalized) ----
    float* orow_a = gout + ((size_t)b * NSEQ + gi0) * DHEAD;
    float* orow_b = orow_a + 8 * DHEAD;
#pragma unroll
    for (int nf = 0; nf < 16; nf++) {
        int d0 = nf * 8 + 2 * lr;
        *(float2*)(orow_a + d0) = make_float2(o[nf][0] * linv_a, o[nf][1] * linv_a);
        *(float2*)(orow_b + d0) = make_float2(o[nf][2] * linv_b, o[nf][3] * linv_b);
    }

    // ---- fold-in rescale: each warp normalizes its own 16 attn rows in-place ----
    {
        float* wbase = gattn + ((size_t)b * NSEQ + (size_t)(qt * TQ + wrow)) * NSEQ;
#pragma unroll 1
        for (int rr = 0; rr < 16; rr++) {
            const float lv = __shfl_sync(0xffffffffu,
                                         (rr < 8) ? linv_a : linv_b, (rr & 7) * 4);
            float* prow = wbase + (size_t)rr * NSEQ;
            for (int j = lane * 4; j < jz; j += 128) {
                float4 v = *(float4*)(prow + j);
                v.x *= lv; v.y *= lv; v.z *= lv; v.w *= lv;
                *(float4*)(prow + j) = v;
            }
        }
    }
}

extern "C" void kernel_launch(void* const* d_in, const int* in_sizes, int n_in,
                              void* d_out, int out_size) {
    const float* q = (const float*)d_in[0];
    const float* k = (const float*)d_in[1];
    const float* v = (const float*)d_in[2];
    // mask (d_in[3]) is a fixed causal mask; applied analytically in-kernel.
    float* attn = (float*)d_out;
    float* out = attn + (size_t)BATCH * NSEQ * NSEQ;

    cudaFuncSetAttribute(attn_kernel, cudaFuncAttributeMaxDynamicSharedMemorySize, SM_BYTES);
    dim3 grid(NSEQ / TQ, BATCH);
    attn_kernel<<<grid, THREADS, SM_BYTES>>>(q, k, v, attn, out);
}

// round 8
// speedup vs baseline: 1.1596x; 1.1596x over previous
#include <cuda_runtime.h>
#include <cstdint>

#define BATCH 32
#define NSEQ 2048
#define DHEAD 128
#define TQ 128
#define TK 64
#define THREADS 256
#define KSTRIDE 136   // Q/K smem row stride (floats); 136 mod 32 = 8 -> LDS.64 row-frags conflict-free
#define VSTRIDE 132   // V smem row stride (floats); 132 mod 32 = 4 -> LDS.32 col-frags conflict-free
#define INV_SCALE 0.088388347648318447f  // 1/sqrt(128)

// smem layout (floats): Q, K[2], V[2]
#define SM_Q_OFF 0
#define SM_K_OFF (TQ * KSTRIDE)
#define SM_V_OFF (SM_K_OFF + 2 * TK * KSTRIDE)
#define SM_FLOATS (SM_V_OFF + 2 * TK * VSTRIDE)
#define SM_BYTES (SM_FLOATS * 4)

// row-sum reciprocals, written by main kernel, read by rescale kernel
__device__ float g_linv[BATCH * NSEQ];

__device__ __forceinline__ float f2tf32(float x) {
    uint32_t u;
    asm("cvt.rna.tf32.f32 %0, %1;" : "=r"(u) : "f"(x));
    return __uint_as_float(u);
}

__device__ __forceinline__ void mma_tf32(float* c, const uint32_t* a, const uint32_t* b) {
    asm volatile(
        "mma.sync.aligned.m16n8k8.row.col.f32.tf32.tf32.f32 "
        "{%0,%1,%2,%3},{%4,%5,%6,%7},{%8,%9},{%0,%1,%2,%3};\n"
        : "+f"(c[0]), "+f"(c[1]), "+f"(c[2]), "+f"(c[3])
        : "r"(a[0]), "r"(a[1]), "r"(a[2]), "r"(a[3]), "r"(b[0]), "r"(b[1]));
}

__device__ __forceinline__ float4 cvt4(float4 v) {
    return make_float4(f2tf32(v.x), f2tf32(v.y), f2tf32(v.z), f2tf32(v.w));
}

// plain row-major copy (tf32-rounded): unit u -> row u>>5, float4-chunk u&31
template <int STRIDE>
__device__ __forceinline__ void sts_unit(float* dst, int u, float4 v) {
    *(float4*)(dst + (u >> 5) * STRIDE + (u & 31) * 4) = cvt4(v);
}

__global__ void __launch_bounds__(THREADS, 1)
attn_kernel(const float* __restrict__ gq, const float* __restrict__ gk,
            const float* __restrict__ gv, float* __restrict__ gattn,
            float* __restrict__ gout) {
    extern __shared__ float sm[];
    float* Qs = sm + SM_Q_OFF;

    const int qt = blockIdx.x;
    const int b = blockIdx.y;
    const int tid = threadIdx.x;
    const int wid = tid >> 5;
    const int lane = tid & 31;
    const int lq = lane >> 2;  // 0..7
    const int lr = lane & 3;   // 0..3

    const int wrow = wid * 16;                 // warp's first row within q-tile
    const int gi0 = qt * TQ + wrow + lq;       // global query row (pair: gi0, gi0+8)
    const int kt_hi = 2 * qt + 1;              // last key tile touching causal region

    // ---- prologue fills: Q (once), K0, V0 into buffer 0 ----
    {
        const float4* q4 = (const float4*)(gq + ((size_t)b * NSEQ + (size_t)qt * TQ) * DHEAD);
        for (int u = tid; u < TQ * 32; u += THREADS) sts_unit<KSTRIDE>(Qs, u, q4[u]);
        const float4* k4 = (const float4*)(gk + (size_t)b * NSEQ * DHEAD);
        for (int u = tid; u < TK * 32; u += THREADS) sts_unit<KSTRIDE>(sm + SM_K_OFF, u, k4[u]);
        const float4* v4 = (const float4*)(gv + (size_t)b * NSEQ * DHEAD);
        for (int u = tid; u < TK * 32; u += THREADS) sts_unit<VSTRIDE>(sm + SM_V_OFF, u, v4[u]);
    }

    float o[16][4];
#pragma unroll
    for (int nf = 0; nf < 16; nf++) {
        o[nf][0] = 0.f; o[nf][1] = 0.f; o[nf][2] = 0.f; o[nf][3] = 0.f;
    }
    float lsum_a = 0.f, lsum_b = 0.f;

    float* attn_row_a = gattn + ((size_t)b * NSEQ + gi0) * NSEQ;
    float* attn_row_b = attn_row_a + (size_t)8 * NSEQ;

    __syncthreads();

    for (int kt = 0; kt <= kt_hi; kt++) {
        const bool has_next = (kt < kt_hi);
        const int cur = kt & 1;
        float* Ks = sm + SM_K_OFF + cur * (TK * KSTRIDE);
        float* Vs = sm + SM_V_OFF + cur * (TK * VSTRIDE);
        float* Kn = sm + SM_K_OFF + (cur ^ 1) * (TK * KSTRIDE);
        float* Vn = sm + SM_V_OFF + (cur ^ 1) * (TK * VSTRIDE);

        // ---- stage next K tile in registers (stored to alt buffer after QK) ----
        float4 kp[8];
        if (has_next) {
            const float4* k4 = (const float4*)(gk + ((size_t)b * NSEQ + (size_t)(kt + 1) * TK) * DHEAD);
#pragma unroll
            for (int j = 0; j < 8; j++) kp[j] = k4[tid + j * THREADS];
        }

        // ---- S = Q K^T  (warp: 16 rows x 64 cols) ----
        // k-slice mapping: MMA k-slot lr -> d = 8*ks+2*lr, slot lr+4 -> d = 8*ks+2*lr+1
        float c[8][4];
#pragma unroll
        for (int nf = 0; nf < 8; nf++) {
            c[nf][0] = 0.f; c[nf][1] = 0.f; c[nf][2] = 0.f; c[nf][3] = 0.f;
        }
#pragma unroll
        for (int ks = 0; ks < 16; ks++) {
            uint32_t a[4];
            float2 a01 = *(const float2*)(Qs + (wrow + lq) * KSTRIDE + ks * 8 + 2 * lr);
            float2 a23 = *(const float2*)(Qs + (wrow + lq + 8) * KSTRIDE + ks * 8 + 2 * lr);
            a[0] = __float_as_uint(a01.x);
            a[2] = __float_as_uint(a01.y);
            a[1] = __float_as_uint(a23.x);
            a[3] = __float_as_uint(a23.y);
#pragma unroll
            for (int nf = 0; nf < 8; nf++) {
                float2 bv = *(const float2*)(Ks + (nf * 8 + lq) * KSTRIDE + ks * 8 + 2 * lr);
                uint32_t bb[2];
                bb[0] = __float_as_uint(bv.x);
                bb[1] = __float_as_uint(bv.y);
                mma_tf32(c[nf], a, bb);
            }
        }

        // ---- flush staged K into alternate buffer (frees kp regs), stage V next ----
        if (has_next) {
#pragma unroll
            for (int j = 0; j < 8; j++) sts_unit<KSTRIDE>(Kn, tid + j * THREADS, kp[j]);
        }
        float4 vp[8];
        if (has_next) {
            const float4* v4 = (const float4*)(gv + ((size_t)b * NSEQ + (size_t)(kt + 1) * TK) * DHEAD);
#pragma unroll
            for (int j = 0; j < 8; j++) vp[j] = v4[tid + j * THREADS];
        }

        // ---- exp (unnormalized), accumulate l, write attn, tf32-round P in regs ----
#pragma unroll
        for (int nf = 0; nf < 8; nf++) {
            int j0 = kt * TK + nf * 8 + 2 * lr;
            float p00 = (j0     <= gi0)     ? __expf(c[nf][0] * INV_SCALE) : 0.f;
            float p01 = (j0 + 1 <= gi0)     ? __expf(c[nf][1] * INV_SCALE) : 0.f;
            float p10 = (j0     <= gi0 + 8) ? __expf(c[nf][2] * INV_SCALE) : 0.f;
            float p11 = (j0 + 1 <= gi0 + 8) ? __expf(c[nf][3] * INV_SCALE) : 0.f;
            lsum_a += p00 + p01;
            lsum_b += p10 + p11;
            *(float2*)(attn_row_a + j0) = make_float2(p00, p01);
            *(float2*)(attn_row_b + j0) = make_float2(p10, p11);
            c[nf][0] = f2tf32(p00);
            c[nf][1] = f2tf32(p01);
            c[nf][2] = f2tf32(p10);
            c[nf][3] = f2tf32(p11);
        }

        // ---- O += P @ V  (A = c-regs; B = V rows, 2x LDS.32 per frag) ----
#pragma unroll
        for (int ks = 0; ks < 8; ks++) {
            uint32_t a[4];
            a[0] = __float_as_uint(c[ks][0]);
            a[1] = __float_as_uint(c[ks][2]);
            a[2] = __float_as_uint(c[ks][1]);
            a[3] = __float_as_uint(c[ks][3]);
            const float* vr0 = Vs + (ks * 8 + 2 * lr) * VSTRIDE + lq;
            const float* vr1 = vr0 + VSTRIDE;
#pragma unroll
            for (int nf = 0; nf < 16; nf++) {
                uint32_t bb[2];
                bb[0] = __float_as_uint(vr0[nf * 8]);
                bb[1] = __float_as_uint(vr1[nf * 8]);
                mma_tf32(o[nf], a, bb);
            }
        }

        // ---- flush staged V into alternate buffer ----
        if (has_next) {
#pragma unroll
            for (int j = 0; j < 8; j++) sts_unit<VSTRIDE>(Vn, tid + j * THREADS, vp[j]);
        }
        __syncthreads();   // single sync: buffer flip
    }

    // ---- row sums (warp-local: full key range per warp) ----
    lsum_a += __shfl_xor_sync(0xffffffffu, lsum_a, 1);
    lsum_a += __shfl_xor_sync(0xffffffffu, lsum_a, 2);
    lsum_b += __shfl_xor_sync(0xffffffffu, lsum_b, 1);
    lsum_b += __shfl_xor_sync(0xffffffffu, lsum_b, 2);
    const float linv_a = 1.0f / lsum_a;
    const float linv_b = 1.0f / lsum_b;
    if (lr == 0) {
        g_linv[b * NSEQ + gi0] = linv_a;
        g_linv[b * NSEQ + gi0 + 8] = linv_b;
    }

    // ---- zero-fill the strictly-masked key region (j >= (kt_hi+1)*64) ----
    {
        const int jz = (kt_hi + 1) * TK;
        if (jz < NSEQ) {
            const int zc4 = (NSEQ - jz) >> 2;
            const float4 z4 = make_float4(0.f, 0.f, 0.f, 0.f);
            float* base = gattn + ((size_t)b * NSEQ + (size_t)qt * TQ) * NSEQ + jz;
            for (int i = tid; i < TQ * zc4; i += THREADS) {
                int r = i / zc4;
                int cc = i - r * zc4;
                *(float4*)(base + (size_t)r * NSEQ + cc * 4) = z4;
            }
        }
    }

    // ---- write O (normalized) ----
    float* orow_a = gout + ((size_t)b * NSEQ + gi0) * DHEAD;
    float* orow_b = orow_a + 8 * DHEAD;
#pragma unroll
    for (int nf = 0; nf < 16; nf++) {
        int d0 = nf * 8 + 2 * lr;
        *(float2*)(orow_a + d0) = make_float2(o[nf][0] * linv_a, o[nf][1] * linv_a);
        *(float2*)(orow_b + d0) = make_float2(o[nf][2] * linv_b, o[nf][3] * linv_b);
    }
}

// rescale the causal (lower-triangular) part of attn by 1/l; one warp per row
__global__ void __launch_bounds__(256)
rescale_kernel(float* __restrict__ gattn) {
    const int row = blockIdx.x * 8 + (threadIdx.x >> 5);  // b*NSEQ + i
    const int lane = threadIdx.x & 31;
    const int i = row & (NSEQ - 1);
    const float linv = g_linv[row];
    float* p = gattn + (size_t)row * NSEQ;
    const int n = i + 1;          // valid entries: j in [0, i]
    const int nvec = n & ~3;      // float4-aligned prefix
    for (int j = lane * 4; j < nvec; j += 128) {
        float4 v = *(float4*)(p + j);
        v.x *= linv; v.y *= linv; v.z *= linv; v.w *= linv;
        *(float4*)(p + j) = v;
    }
    if (lane < (n - nvec)) {
        p[nvec + lane] *= linv;
    }
}

extern "C" void kernel_launch(void* const* d_in, const int* in_sizes, int n_in,
                              void* d_out, int out_size) {
    const float* q = (const float*)d_in[0];
    const float* k = (const float*)d_in[1];
    const float* v = (const float*)d_in[2];
    // mask (d_in[3]) is a fixed causal mask; applied analytically in-kernel.
    float* attn = (float*)d_out;
    float* out = attn + (size_t)BATCH * NSEQ * NSEQ;

    cudaFuncSetAttribute(attn_kernel, cudaFuncAttributeMaxDynamicSharedMemorySize, SM_BYTES);
    dim3 grid(NSEQ / TQ, BATCH);
    attn_kernel<<<grid, THREADS, SM_BYTES>>>(q, k, v, attn, out);

    // normalize the causal part of attn (masked part is already exact zeros)
    rescale_kernel<<<(BATCH * NSEQ) / 8, 256>>>(attn);
}